// round 12
// baseline (speedup 1.0000x reference)
#include <cuda_runtime.h>
#include <cuda_bf16.h>

#define N_NODES 100000
#define N_EDGES 3200000
#define HID 16

// ---------------- device scratch ----------------
__device__ float g_aggs[N_NODES];    // layer-1 scalar segment sum (memset to 0)
__device__ float g_alpha[N_NODES];   // z . (proc_w_rel @ dec_w_rel)
__device__ float g_A[N_NODES];       // init = bg, accumulates alpha => tg
__device__ __align__(16) int2 g_edge[N_EDGES];  // packed {src,dst}
__device__ int   g_is64;
__device__ float g_w1[HID], g_w2[HID], g_w3[HID], g_w4[HID];
__device__ float g_c1, g_c2;

// ---------------- kernels ----------------

// Tiny prep: block 0 detects int64 vs int32; block 1 folds proc/dec weights.
__global__ void k_prep(const void* ei,
                       const float* __restrict__ proc_w_rel,
                       const float* __restrict__ proc_w_root,
                       const float* __restrict__ proc_b,
                       const float* __restrict__ dec_w_rel,
                       const float* __restrict__ dec_w_root) {
    if (blockIdx.x == 0) {
        // int64 detection: node ids < 1e5 << 2^32 -> int64 data has zero high halves.
        const unsigned long long* p = (const unsigned long long*)ei;
        int bad = 0;
        for (int k = threadIdx.x; k < 256; k += blockDim.x)
            if ((p[k] >> 32) != 0ull) bad = 1;
        bad = __syncthreads_or(bad);
        if (threadIdx.x == 0) g_is64 = bad ? 0 : 1;
    } else if (threadIdx.x < 64) {
        int t = threadIdx.x;
        int g = t & 15;
        int which = t >> 4;
        const float* M = (which < 2) ? proc_w_rel : proc_w_root;
        const float* v = (which & 1) ? dec_w_root : dec_w_rel;
        float acc = 0.f;
#pragma unroll
        for (int f = 0; f < HID; f++) acc = fmaf(M[g * HID + f], v[f], acc);
        if (which == 0) g_w1[g] = acc;
        else if (which == 1) g_w2[g] = acc;
        else if (which == 2) g_w3[g] = acc;
        else g_w4[g] = acc;
        if (t == 0) {
            float a = 0.f, b = 0.f;
#pragma unroll
            for (int f = 0; f < HID; f++) {
                a = fmaf(proc_b[f], dec_w_rel[f], a);
                b = fmaf(proc_b[f], dec_w_root[f], b);
            }
            g_c1 = a; g_c2 = b;
        }
    }
}

// Edge pass 1: pack edge list to int2 {src,dst} AND scatter x scalar.
// 1 edge per thread. Streaming reads use evict-first (.cs) to protect the
// hot node arrays' L2 residency.
__global__ void __launch_bounds__(256) k_edge1(const void* ei, const float* __restrict__ x) {
    int e = blockIdx.x * blockDim.x + threadIdx.x;
    if (e >= N_EDGES) return;
    int s, d;
    if (g_is64) {
        const long long* p = (const long long*)ei;
        s = (int)__ldcs(&p[e]);
        d = (int)__ldcs(&p[(long long)N_EDGES + e]);
    } else {
        const int* p = (const int*)ei;
        s = __ldcs(&p[e]);
        d = __ldcs(&p[N_EDGES + e]);
    }
    g_edge[e] = make_int2(s, d);
    atomicAdd(&g_aggs[d], __ldg(&x[s]));
}

// Node pass 1: z = relu(enc), project onto folded directions.
// Accumulate-initialize: g_A = bg (edge2 then produces tg directly),
//                        out  = dc (edge3 then produces pre-relu output in-place).
__global__ void k_node1(const float* __restrict__ x,
                        const float* __restrict__ enc_w_rel,
                        const float* __restrict__ enc_w_root,
                        const float* __restrict__ enc_b,
                        const float* __restrict__ dec_b,
                        float* __restrict__ out) {
    __shared__ float sWrel[HID], sWroot[HID], sB[HID];
    __shared__ float s1[HID], s2[HID], s3[HID], s4[HID];
    __shared__ float sc1, sc2, sDb;
    int t = threadIdx.x;
    if (t < HID) {
        sWrel[t] = enc_w_rel[t]; sWroot[t] = enc_w_root[t]; sB[t] = enc_b[t];
        s1[t] = g_w1[t]; s2[t] = g_w2[t]; s3[t] = g_w3[t]; s4[t] = g_w4[t];
    }
    if (t == 0) { sc1 = g_c1; sc2 = g_c2; sDb = dec_b[0]; }
    __syncthreads();

    int i = blockIdx.x * blockDim.x + t;
    if (i >= N_NODES) return;

    float a  = g_aggs[i];
    float xv = __ldg(&x[i]);
    float al = 0.f, ga = 0.f, be = 0.f, de = 0.f;
#pragma unroll
    for (int f = 0; f < HID; f++) {
        float z = fmaxf(fmaf(a, sWrel[f], fmaf(xv, sWroot[f], sB[f])), 0.f);
        al = fmaf(z, s1[f], al);
        ga = fmaf(z, s2[f], ga);
        be = fmaf(z, s3[f], be);
        de = fmaf(z, s4[f], de);
    }
    g_alpha[i] = al;
    g_A[i]     = be + ga + sc1;      // bg  (accumulator init)
    out[i]     = de + sc2 + sDb;     // dc  (accumulator init, lives in d_out)
}

// Edge pass 2: A[dst] += alpha[src].  After this, g_A == tg.
__global__ void __launch_bounds__(256) k_edge2() {
    int e = blockIdx.x * blockDim.x + threadIdx.x;
    if (e >= N_EDGES) return;
    int2 sd = __ldcs(&g_edge[e]);
    atomicAdd(&g_A[sd.y], __ldg(&g_alpha[sd.x]));
}

// Edge pass 3: out[dst] += tg[src]  (tg == g_A), accumulating into d_out.
__global__ void __launch_bounds__(256) k_edge3(float* __restrict__ out) {
    int e = blockIdx.x * blockDim.x + threadIdx.x;
    if (e >= N_EDGES) return;
    int2 sd = __ldcs(&g_edge[e]);
    atomicAdd(&out[sd.y], __ldg(&g_A[sd.x]));
}

// Node pass 3: in-place relu on d_out.
__global__ void k_node3(float* __restrict__ out) {
    int i = blockIdx.x * blockDim.x + threadIdx.x;
    if (i >= N_NODES) return;
    out[i] = fmaxf(out[i], 0.f);
}

// ---------------- launch ----------------
extern "C" void kernel_launch(void* const* d_in, const int* in_sizes, int n_in,
                              void* d_out, int out_size) {
    const float* x          = (const float*)d_in[0];
    const void*  ei         = d_in[1];
    const float* enc_w_rel  = (const float*)d_in[2];
    const float* enc_w_root = (const float*)d_in[3];
    const float* enc_b      = (const float*)d_in[4];
    const float* proc_w_rel = (const float*)d_in[5];
    const float* proc_w_root= (const float*)d_in[6];
    const float* proc_b     = (const float*)d_in[7];
    const float* dec_w_rel  = (const float*)d_in[8];
    const float* dec_w_root = (const float*)d_in[9];
    const float* dec_b      = (const float*)d_in[10];
    float* out = (float*)d_out;

    const int B = 256;
    const int GN = (N_NODES + B - 1) / B;
    const int GE = (N_EDGES + B - 1) / B;

    // Zero the layer-1 accumulator via a memset node (faster than a kernel).
    void* aggs_ptr = nullptr;
    cudaGetSymbolAddress(&aggs_ptr, g_aggs);
    cudaMemsetAsync(aggs_ptr, 0, N_NODES * sizeof(float));

    k_prep<<<2, 256>>>(ei, proc_w_rel, proc_w_root, proc_b, dec_w_rel, dec_w_root);
    k_edge1<<<GE, B>>>(ei, x);
    k_node1<<<GN, B>>>(x, enc_w_rel, enc_w_root, enc_b, dec_b, out);
    k_edge2<<<GE, B>>>();
    k_edge3<<<GE, B>>>(out);
    k_node3<<<GN, B>>>(out);
}

// round 13
// speedup vs baseline: 1.0405x; 1.0405x over previous
#include <cuda_runtime.h>
#include <cuda_bf16.h>

#define N_NODES 100000
#define N_EDGES 3200000
#define HID 16

// ---------------- device scratch ----------------
__device__ float g_aggs[N_NODES];    // layer-1 scalar segment sum (memset to 0)
__device__ float g_alpha[N_NODES];   // z . (proc_w_rel @ dec_w_rel)
__device__ float g_A[N_NODES];       // init = bg, accumulates alpha => tg
__device__ float g_T[N_NODES];       // init = dc, accumulates tg => pre-relu out
__device__ __align__(16) int2 g_edge[N_EDGES];  // packed {src,dst}
__device__ int   g_is64;
__device__ float g_w1[HID], g_w2[HID], g_w3[HID], g_w4[HID];
__device__ float g_c1, g_c2;

// ---------------- kernels ----------------

// Tiny prep: block 0 detects int64 vs int32; block 1 folds proc/dec weights.
__global__ void k_prep(const void* ei,
                       const float* __restrict__ proc_w_rel,
                       const float* __restrict__ proc_w_root,
                       const float* __restrict__ proc_b,
                       const float* __restrict__ dec_w_rel,
                       const float* __restrict__ dec_w_root) {
    if (blockIdx.x == 0) {
        // int64 detection: node ids < 1e5 << 2^32 -> int64 data has zero high halves.
        const unsigned long long* p = (const unsigned long long*)ei;
        int bad = 0;
        for (int k = threadIdx.x; k < 256; k += blockDim.x)
            if ((p[k] >> 32) != 0ull) bad = 1;
        bad = __syncthreads_or(bad);
        if (threadIdx.x == 0) g_is64 = bad ? 0 : 1;
    } else if (threadIdx.x < 64) {
        int t = threadIdx.x;
        int g = t & 15;
        int which = t >> 4;
        const float* M = (which < 2) ? proc_w_rel : proc_w_root;
        const float* v = (which & 1) ? dec_w_root : dec_w_rel;
        float acc = 0.f;
#pragma unroll
        for (int f = 0; f < HID; f++) acc = fmaf(M[g * HID + f], v[f], acc);
        if (which == 0) g_w1[g] = acc;
        else if (which == 1) g_w2[g] = acc;
        else if (which == 2) g_w3[g] = acc;
        else g_w4[g] = acc;
        if (t == 0) {
            float a = 0.f, b = 0.f;
#pragma unroll
            for (int f = 0; f < HID; f++) {
                a = fmaf(proc_b[f], dec_w_rel[f], a);
                b = fmaf(proc_b[f], dec_w_root[f], b);
            }
            g_c1 = a; g_c2 = b;
        }
    }
}

// Edge pass 1: pack edge list to int2 {src,dst} AND scatter x scalar.
// 1 edge per thread, default cache policy (evict-first regressed).
__global__ void __launch_bounds__(256) k_edge1(const void* ei, const float* __restrict__ x) {
    int e = blockIdx.x * blockDim.x + threadIdx.x;
    if (e >= N_EDGES) return;
    int s, d;
    if (g_is64) {
        const long long* p = (const long long*)ei;
        s = (int)p[e];
        d = (int)p[(long long)N_EDGES + e];
    } else {
        const int* p = (const int*)ei;
        s = p[e];
        d = p[N_EDGES + e];
    }
    g_edge[e] = make_int2(s, d);
    atomicAdd(&g_aggs[d], __ldg(&x[s]));
}

// Node pass 1: z = relu(enc), project onto folded directions.
// Accumulate-initialize: g_A = bg (edge2 then produces tg directly),
//                        g_T = dc (edge3 then produces pre-relu output).
__global__ void k_node1(const float* __restrict__ x,
                        const float* __restrict__ enc_w_rel,
                        const float* __restrict__ enc_w_root,
                        const float* __restrict__ enc_b,
                        const float* __restrict__ dec_b) {
    __shared__ float sWrel[HID], sWroot[HID], sB[HID];
    __shared__ float s1[HID], s2[HID], s3[HID], s4[HID];
    __shared__ float sc1, sc2, sDb;
    int t = threadIdx.x;
    if (t < HID) {
        sWrel[t] = enc_w_rel[t]; sWroot[t] = enc_w_root[t]; sB[t] = enc_b[t];
        s1[t] = g_w1[t]; s2[t] = g_w2[t]; s3[t] = g_w3[t]; s4[t] = g_w4[t];
    }
    if (t == 0) { sc1 = g_c1; sc2 = g_c2; sDb = dec_b[0]; }
    __syncthreads();

    int i = blockIdx.x * blockDim.x + t;
    if (i >= N_NODES) return;

    float a  = g_aggs[i];
    float xv = __ldg(&x[i]);
    float al = 0.f, ga = 0.f, be = 0.f, de = 0.f;
#pragma unroll
    for (int f = 0; f < HID; f++) {
        float z = fmaxf(fmaf(a, sWrel[f], fmaf(xv, sWroot[f], sB[f])), 0.f);
        al = fmaf(z, s1[f], al);
        ga = fmaf(z, s2[f], ga);
        be = fmaf(z, s3[f], be);
        de = fmaf(z, s4[f], de);
    }
    g_alpha[i] = al;
    g_A[i]     = be + ga + sc1;      // bg  (accumulator init)
    g_T[i]     = de + sc2 + sDb;     // dc  (accumulator init)
}

// Edge pass 2: A[dst] += alpha[src].  After this, g_A == tg.  Block = 512.
__global__ void __launch_bounds__(512) k_edge2() {
    int e = blockIdx.x * blockDim.x + threadIdx.x;
    if (e >= N_EDGES) return;
    int2 sd = g_edge[e];
    atomicAdd(&g_A[sd.y], __ldg(&g_alpha[sd.x]));
}

// Edge pass 3: T[dst] += tg[src]  (tg == g_A).  Block = 512.
__global__ void __launch_bounds__(512) k_edge3() {
    int e = blockIdx.x * blockDim.x + threadIdx.x;
    if (e >= N_EDGES) return;
    int2 sd = g_edge[e];
    atomicAdd(&g_T[sd.y], __ldg(&g_A[sd.x]));
}

// Node pass 3: out = relu(T).
__global__ void k_node3(float* __restrict__ out) {
    int i = blockIdx.x * blockDim.x + threadIdx.x;
    if (i >= N_NODES) return;
    out[i] = fmaxf(__ldg(&g_T[i]), 0.f);
}

// ---------------- launch ----------------
extern "C" void kernel_launch(void* const* d_in, const int* in_sizes, int n_in,
                              void* d_out, int out_size) {
    const float* x          = (const float*)d_in[0];
    const void*  ei         = d_in[1];
    const float* enc_w_rel  = (const float*)d_in[2];
    const float* enc_w_root = (const float*)d_in[3];
    const float* enc_b      = (const float*)d_in[4];
    const float* proc_w_rel = (const float*)d_in[5];
    const float* proc_w_root= (const float*)d_in[6];
    const float* proc_b     = (const float*)d_in[7];
    const float* dec_w_rel  = (const float*)d_in[8];
    const float* dec_w_root = (const float*)d_in[9];
    const float* dec_b      = (const float*)d_in[10];
    float* out = (float*)d_out;

    const int B = 256;
    const int GN  = (N_NODES + B - 1) / B;
    const int GE  = (N_EDGES + B - 1) / B;        // block 256
    const int GE5 = (N_EDGES + 511) / 512;        // block 512

    // Zero the layer-1 accumulator via a memset node (faster than a kernel).
    void* aggs_ptr = nullptr;
    cudaGetSymbolAddress(&aggs_ptr, g_aggs);
    cudaMemsetAsync(aggs_ptr, 0, N_NODES * sizeof(float));

    k_prep<<<2, 256>>>(ei, proc_w_rel, proc_w_root, proc_b, dec_w_rel, dec_w_root);
    k_edge1<<<GE, B>>>(ei, x);
    k_node1<<<GN, B>>>(x, enc_w_rel, enc_w_root, enc_b, dec_b);
    k_edge2<<<GE5, 512>>>();
    k_edge3<<<GE5, 512>>>();
    k_node3<<<GN, B>>>(out);
}